// round 10
// baseline (speedup 1.0000x reference)
#include <cuda_runtime.h>
#include <math.h>

#define BQ 300   // predictions (columns of LSA)
#define BT 50    // truths (rows of LSA)
#define NB 32    // batch
#define NTHREADS 320
#define KPL 10   // columns per lane (32*10 = 320 >= 300)

#define KEY_UMAX 0xFFFFFFFFFFFFFFFFULL

// IEEE-754 double -> uint64 order-preserving map (no NaNs in play).
__device__ __forceinline__ unsigned long long dmap(double d) {
    unsigned long long b = (unsigned long long)__double_as_longlong(d);
    return (b & 0x8000000000000000ULL) ? ~b : (b ^ 0x8000000000000000ULL);
}
__device__ __forceinline__ double dunmap(unsigned long long k) {
    unsigned long long b = (k & 0x8000000000000000ULL) ? (k ^ 0x8000000000000000ULL) : ~k;
    return __longlong_as_double((long long)b);
}

extern __shared__ float costm[];   // BT*BQ floats (60000 B dynamic SMEM)

__global__ __launch_bounds__(NTHREADS, 1)
void hungarian_kernel(const float* __restrict__ pred,
                      const float* __restrict__ truth,
                      float* __restrict__ out)
{
    __shared__ float  sp[BQ * 4];
    __shared__ float  st[BT * 4];
    __shared__ double u_s[BT];
    __shared__ double ss[BQ];       // frozen shortest at selection time
    __shared__ short  path_s[BQ];
    __shared__ short  row4col[BQ];
    __shared__ short  col4row[BT];

    const int b   = blockIdx.x;
    const int tid = threadIdx.x;

    // Phase 0: stage boxes + init matching state
    for (int k = tid; k < BQ * 4; k += NTHREADS) sp[k] = pred[b * BQ * 4 + k];
    for (int k = tid; k < BT * 4; k += NTHREADS) st[k] = truth[b * BT * 4 + k];
    for (int k = tid; k < BQ; k += NTHREADS) row4col[k] = -1;
    for (int k = tid; k < BT; k += NTHREADS) { col4row[k] = -1; u_s[k] = 0.0; }
    __syncthreads();

    // Phase 1: precompute full 50x300 cost matrix (all 320 threads)
    for (int e = tid; e < BT * BQ; e += NTHREADS) {
        const int i = e / BQ;
        const int j = e - i * BQ;
        const float pcx = sp[j*4+0], pcy = sp[j*4+1], pw = sp[j*4+2], ph = sp[j*4+3];
        const float tcx = st[i*4+0], tcy = st[i*4+1], tw = st[i*4+2], th = st[i*4+3];

        float px0 = pcx - 0.5f * pw, py0 = pcy - 0.5f * ph;
        float px1 = pcx + 0.5f * pw, py1 = pcy + 0.5f * ph;
        float parea = (px1 - px0) * (py1 - py0);

        float l1 = fabsf(pcx - tcx) + fabsf(pcy - tcy)
                 + fabsf(pw - tw)  + fabsf(ph - th);
        float tx0 = tcx - 0.5f * tw, ty0 = tcy - 0.5f * th;
        float tx1 = tcx + 0.5f * tw, ty1 = tcy + 0.5f * th;
        float tarea = (tx1 - tx0) * (ty1 - ty0);
        float ltx = fmaxf(px0, tx0), lty = fmaxf(py0, ty0);
        float rbx = fminf(px1, tx1), rby = fminf(py1, ty1);
        float wx = fmaxf(rbx - ltx, 0.f), wy = fmaxf(rby - lty, 0.f);
        float inter = wx * wy;
        float uni   = parea + tarea - inter;
        float iou   = inter / uni;
        float ex0 = fminf(px0, tx0), ey0 = fminf(py0, ty0);
        float ex1 = fmaxf(px1, tx1), ey1 = fmaxf(py1, ty1);
        float ew = fmaxf(ex1 - ex0, 0.f), eh = fmaxf(ey1 - ey0, 0.f);
        float ae   = ew * eh;
        float giou = iou - (ae - uni) / ae;
        costm[e]   = 5.0f * l1 - 2.0f * giou;
    }
    __syncthreads();

    // Phase 2: single-warp JV solver, no block barriers from here on.
    if (tid >= 32) return;
    const int lane = tid;

    double             vv[KPL];     // column duals v, lane-resident
    unsigned long long dkey[KPL];   // order-mapped shortest keys
    unsigned int valid = 0;
    #pragma unroll
    for (int k = 0; k < KPL; k++) {
        vv[k] = 0.0;
        if (lane + 32 * k < BQ) valid |= (1u << k);
    }
    const unsigned long long KEY_INF = dmap(INFINITY);

    for (int cur = 0; cur < BT; cur++) {
        unsigned int avail = valid, sel = 0;
        #pragma unroll
        for (int k = 0; k < KPL; k++)
            dkey[k] = (valid >> k & 1u) ? KEY_INF : KEY_UMAX;

        int    i    = cur;
        double mv   = 0.0;
        double u_i  = u_s[cur];
        int    sink = -1;

        while (sink < 0) {
            // Relax all still-available columns owned by this lane
            #pragma unroll
            for (int k = 0; k < KPL; k++) {
                if (avail & (1u << k)) {
                    const int j = lane + 32 * k;
                    double d = ((mv + (double)costm[i * BQ + j]) - u_i) - vv[k];
                    unsigned long long nk = dmap(d);
                    if (nk < dkey[k]) { dkey[k] = nk; path_s[j] = (short)i; }
                }
            }
            // Lane-local argmin (ascending k => lowest j kept on ties)
            unsigned long long bk = KEY_UMAX;
            int bj = 1024;
            #pragma unroll
            for (int k = 0; k < KPL; k++) {
                if (dkey[k] < bk) { bk = dkey[k]; bj = lane + 32 * k; }
            }
            // Warp butterfly argmin, lowest-j tie-break (matches np.argmin)
            #pragma unroll
            for (int off = 16; off > 0; off >>= 1) {
                unsigned long long ok = __shfl_xor_sync(0xffffffffu, bk, off);
                int                oj = __shfl_xor_sync(0xffffffffu, bj, off);
                if (ok < bk || (ok == bk && oj < bj)) { bk = ok; bj = oj; }
            }
            const double mvn = dunmap(bk);
            if (lane == (bj & 31)) {              // owner freezes its column
                const int k = bj >> 5;
                dkey[k] = KEY_UMAX;
                avail &= ~(1u << k);
                sel   |=  (1u << k);
                ss[bj] = mvn;                     // frozen shortest[j]
            }
            const int r = row4col[bj];            // uniform LDS broadcast
            mv = mvn;
            if (r < 0) sink = bj;
            else { i = r; u_i = u_s[i]; }
        }

        // Dual updates (pre-augmentation, exactly the reference algebra)
        __syncwarp();
        #pragma unroll
        for (int k = 0; k < KPL; k++) {
            if (sel & (1u << k)) {
                const int j = lane + 32 * k;
                const double delta = mv - ss[j];
                vv[k] -= delta;                        // v[j] -= mv - shortest[j]
                const int r = row4col[j];              // pre-augment matching
                if (r >= 0) u_s[r] += delta;           // u[r] += mv - shortest[col4row[r]]
            }
        }
        if (lane == 0) u_s[cur] += mv;
        __syncwarp();

        // Augment along the path (lane 0, <= BT hops)
        if (lane == 0) {
            int j = sink;
            while (true) {
                const int i2 = path_s[j];
                row4col[j] = (short)i2;
                const int tmp = col4row[i2];
                col4row[i2] = (short)j;
                j = tmp;
                if (i2 == cur) break;
            }
        }
        __syncwarp();
    }

    // Output: pairs sorted by pred index; rank = #(assigned preds < mine).
    for (int t = lane; t < BT; t += 32) {
        const int my = col4row[t];
        int rank = 0;
        for (int t2 = 0; t2 < BT; t2++) rank += (col4row[t2] < my) ? 1 : 0;
        out[b * 2 * BT + rank]      = (float)my;
        out[b * 2 * BT + BT + rank] = (float)t;
    }
}

extern "C" void kernel_launch(void* const* d_in, const int* in_sizes, int n_in,
                              void* d_out, int out_size)
{
    // pred_boxes (32x300x4) is the LARGER buffer in either units/order.
    const float* pred;
    const float* truth;
    if (n_in >= 2 && in_sizes[1] > in_sizes[0]) {
        pred  = (const float*)d_in[1];
        truth = (const float*)d_in[0];
    } else {
        pred  = (const float*)d_in[0];
        truth = (const float*)d_in[1];
    }
    (void)out_size;

    const int dyn_smem = BT * BQ * (int)sizeof(float);   // 60000 B
    cudaFuncSetAttribute(hungarian_kernel,
                         cudaFuncAttributeMaxDynamicSharedMemorySize, dyn_smem);
    hungarian_kernel<<<NB, NTHREADS, dyn_smem>>>(pred, truth, (float*)d_out);
}

// round 11
// speedup vs baseline: 3.3806x; 3.3806x over previous
#include <cuda_runtime.h>
#include <math.h>

#define BQ 300   // predictions (columns of LSA)
#define BT 50    // truths (rows of LSA)
#define NB 32    // batch
#define NTHREADS 320
#define KPL 10   // columns per lane (32*10 = 320 >= 300)
#define LLMAX 0x7FFFFFFFFFFFFFFFLL

// Fixed-point scale 2^40: f32 costs convert exactly (24-bit mantissa, |c|<32);
// all solver arithmetic becomes exact int64 -> no FP64 in the hot loop.
#define FIXSCALE 1099511627776.0

extern __shared__ long long cfix[];   // BT*BQ int64 costs (120000 B dynamic)

// Warp-wide argmin over (int64 key, int idx), lowest-idx tie-break.
// Uses REDUX.MIN.U32 three times instead of a 5-round 64-bit butterfly.
__device__ __forceinline__ void warp_argmin64(long long key, int idx,
                                              long long& okey, int& oidx)
{
    unsigned hi = (unsigned)(((unsigned long long)key) >> 32) ^ 0x80000000u;
    unsigned lo = (unsigned)((unsigned long long)key);
    unsigned mh = __reduce_min_sync(0xffffffffu, hi);
    unsigned lo2 = (hi == mh) ? lo : 0xFFFFFFFFu;
    unsigned ml = __reduce_min_sync(0xffffffffu, lo2);
    unsigned ji = (hi == mh && lo == ml) ? (unsigned)idx : 0xFFFFFFFFu;
    unsigned mj = __reduce_min_sync(0xffffffffu, ji);
    okey = (long long)((((unsigned long long)(mh ^ 0x80000000u)) << 32) | ml);
    oidx = (int)mj;
}

__global__ __launch_bounds__(NTHREADS, 1)
void hungarian_kernel(const float* __restrict__ pred,
                      const float* __restrict__ truth,
                      float* __restrict__ out)
{
    __shared__ float     sp[BQ * 4];
    __shared__ float     st[BT * 4];
    __shared__ long long u_s[BT];     // row duals (fixed-point)
    __shared__ long long ss64[BQ];    // frozen shortest at selection
    __shared__ long long rm[BT];      // row minima (init phase)
    __shared__ int       rj[BT];      // row argmin  (init phase)
    __shared__ short     path_s[BQ];
    __shared__ short     row4col[BQ];
    __shared__ short     col4row[BT];

    const int b   = blockIdx.x;
    const int tid = threadIdx.x;

    // Phase 0: stage boxes + init matching state
    for (int k = tid; k < BQ * 4; k += NTHREADS) sp[k] = pred[b * BQ * 4 + k];
    for (int k = tid; k < BT * 4; k += NTHREADS) st[k] = truth[b * BT * 4 + k];
    for (int k = tid; k < BQ; k += NTHREADS) row4col[k] = -1;
    for (int k = tid; k < BT; k += NTHREADS) col4row[k] = -1;
    __syncthreads();

    // Phase 1: cost matrix (identical f32 expression to the passing kernel),
    // converted exactly to int64 fixed point.
    for (int e = tid; e < BT * BQ; e += NTHREADS) {
        const int i = e / BQ;
        const int j = e - i * BQ;
        const float pcx = sp[j*4+0], pcy = sp[j*4+1], pw = sp[j*4+2], ph = sp[j*4+3];
        const float tcx = st[i*4+0], tcy = st[i*4+1], tw = st[i*4+2], th = st[i*4+3];

        float px0 = pcx - 0.5f * pw, py0 = pcy - 0.5f * ph;
        float px1 = pcx + 0.5f * pw, py1 = pcy + 0.5f * ph;
        float parea = (px1 - px0) * (py1 - py0);

        float l1 = fabsf(pcx - tcx) + fabsf(pcy - tcy)
                 + fabsf(pw - tw)  + fabsf(ph - th);
        float tx0 = tcx - 0.5f * tw, ty0 = tcy - 0.5f * th;
        float tx1 = tcx + 0.5f * tw, ty1 = tcy + 0.5f * th;
        float tarea = (tx1 - tx0) * (ty1 - ty0);
        float ltx = fmaxf(px0, tx0), lty = fmaxf(py0, ty0);
        float rbx = fminf(px1, tx1), rby = fminf(py1, ty1);
        float wx = fmaxf(rbx - ltx, 0.f), wy = fmaxf(rby - lty, 0.f);
        float inter = wx * wy;
        float uni   = parea + tarea - inter;
        float iou   = inter / uni;
        float ex0 = fminf(px0, tx0), ey0 = fminf(py0, ty0);
        float ex1 = fmaxf(px1, tx1), ey1 = fmaxf(py1, ty1);
        float ew = fmaxf(ex1 - ex0, 0.f), eh = fmaxf(ey1 - ey0, 0.f);
        float ae   = ew * eh;
        float giou = iou - (ae - uni) / ae;
        float c    = 5.0f * l1 - 2.0f * giou;

        cfix[e] = __double2ll_rn((double)c * FIXSCALE);
    }
    __syncthreads();

    // Phase 1.5: per-row minima (warp w handles rows w, w+10, ...)
    {
        const int w = tid >> 5, ln = tid & 31;
        for (int i = w; i < BT; i += NTHREADS / 32) {
            long long bk = LLMAX; int bj = 1 << 20;
            #pragma unroll
            for (int k = 0; k < KPL; k++) {
                const int j = ln + 32 * k;
                if (j < BQ) {
                    const long long c = cfix[i * BQ + j];
                    if (c < bk) { bk = c; bj = j; }
                }
            }
            long long mk; int mj;
            warp_argmin64(bk, bj, mk, mj);
            if (ln == 0) { rm[i] = mk; rj[i] = mj; }
        }
    }
    __syncthreads();

    // Phase 2: single-warp exact JV solver.
    if (tid >= 32) return;
    const int lane = tid;

    // Greedy init: u_i = row min (feasible duals, tight matched edges).
    if (lane == 0) {
        for (int i = 0; i < BT; i++) {
            u_s[i] = rm[i];
            const int j = rj[i];
            if (row4col[j] < 0) { row4col[j] = (short)i; col4row[i] = (short)j; }
        }
    }
    __syncwarp();

    long long vv64[KPL];              // column duals v (lane-resident)
    long long sd[KPL];                // shortest distances
    unsigned  valid = 0;
    #pragma unroll
    for (int k = 0; k < KPL; k++) {
        vv64[k] = 0;
        if (lane + 32 * k < BQ) valid |= (1u << k);
    }

    for (int cur = 0; cur < BT; cur++) {
        if (col4row[cur] >= 0) continue;   // assigned by greedy init

        unsigned avail = valid, sel = 0;
        #pragma unroll
        for (int k = 0; k < KPL; k++) sd[k] = LLMAX;
        long long lbk = LLMAX; int lbj = 1 << 20;   // lane-local running argmin

        int       i = cur, sink = -1;
        long long mv = 0, u_i = u_s[cur];

        for (int guard = 0; guard <= BQ && sink < 0; guard++) {
            // Relax all available columns owned by this lane (pure int64 ALU)
            const long long  s    = mv - u_i;
            const long long* crow = &cfix[i * BQ];
            #pragma unroll
            for (int k = 0; k < KPL; k++) {
                if (avail & (1u << k)) {
                    const int j = lane + 32 * k;
                    const long long d = s + (crow[j] - vv64[k]);
                    if (d < sd[k]) {
                        sd[k] = d;
                        path_s[j] = (short)i;
                        if (d < lbk) { lbk = d; lbj = j; }
                    }
                }
            }
            long long mk; int mj;
            warp_argmin64(lbk, lbj, mk, mj);
            mv = mk;
            if (lane == (mj & 31)) {              // winner freezes its column
                const int kk = mj >> 5;
                sd[kk] = LLMAX;
                avail &= ~(1u << kk);
                sel   |=  (1u << kk);
                ss64[mj] = mk;
                lbk = LLMAX; lbj = 1 << 20;       // rescan lane best
                #pragma unroll
                for (int k2 = 0; k2 < KPL; k2++)
                    if ((avail & (1u << k2)) && sd[k2] < lbk) {
                        lbk = sd[k2]; lbj = lane + 32 * k2;
                    }
            }
            const int r = row4col[mj];
            if (r < 0) sink = mj;
            else { i = r; u_i = u_s[i]; }
        }
        __syncwarp();

        // Dual updates (pre-augmentation; exact integer algebra)
        #pragma unroll
        for (int k = 0; k < KPL; k++) {
            if (sel & (1u << k)) {
                const int j = lane + 32 * k;
                const long long delta = mv - ss64[j];
                vv64[k] -= delta;                 // v[j] -= mv - shortest[j]
                const int r = row4col[j];         // pre-augment matching
                if (r >= 0) u_s[r] += delta;      // distinct r per lane/k
            }
        }
        if (lane == 0) u_s[cur] += mv;
        __syncwarp();

        // Augment along the path (lane 0)
        if (lane == 0) {
            int j = sink;
            while (j >= 0) {
                const int i2 = path_s[j];
                row4col[j] = (short)i2;
                const int tmp = col4row[i2];
                col4row[i2] = (short)j;
                j = tmp;
                if (i2 == cur) break;
            }
        }
        __syncwarp();
    }

    // Output (float32): pairs sorted by pred index; rank = #(assigned preds < mine)
    for (int t = lane; t < BT; t += 32) {
        const int my = col4row[t];
        int rank = 0;
        for (int t2 = 0; t2 < BT; t2++) rank += (col4row[t2] < my) ? 1 : 0;
        out[b * 2 * BT + rank]      = (float)my;
        out[b * 2 * BT + BT + rank] = (float)t;
    }
}

extern "C" void kernel_launch(void* const* d_in, const int* in_sizes, int n_in,
                              void* d_out, int out_size)
{
    // pred_boxes (32x300x4) is the LARGER buffer in either units/order.
    const float* pred;
    const float* truth;
    if (n_in >= 2 && in_sizes[1] > in_sizes[0]) {
        pred  = (const float*)d_in[1];
        truth = (const float*)d_in[0];
    } else {
        pred  = (const float*)d_in[0];
        truth = (const float*)d_in[1];
    }
    (void)out_size;

    const int dyn_smem = BT * BQ * (int)sizeof(long long);   // 120000 B
    cudaFuncSetAttribute(hungarian_kernel,
                         cudaFuncAttributeMaxDynamicSharedMemorySize, dyn_smem);
    hungarian_kernel<<<NB, NTHREADS, dyn_smem>>>(pred, truth, (float*)d_out);
}